// round 6
// baseline (speedup 1.0000x reference)
#include <cuda_runtime.h>
#include <float.h>

#define NROWS 16384
#define DIM   2048
#define DSTR  2049   // initc row stride (D+1)
#define KC    1000

// ---------- scratch (__device__ globals; no allocation) ----------
__device__ float g_inv[NROWS];                    // 1/sqrt(sum f^2 + 1) per row
__device__ float g_halfc[1024];                   // 0.5 * ||c||^2 (all D+1 cols)
__device__ float g_clast[1024];                   // c[D] (bias column)
__device__ float g_cpad[(size_t)KC * DIM];        // centers[:, :DIM], contiguous
__device__ float g_S[(size_t)NROWS * KC];         // raw dot(feats_m, c_n[:DIM])

// ---------- center prep: copy + 0.5||c||^2 in fp64 ----------
__global__ void k_prep_centers(const float* __restrict__ C) {
    int k = blockIdx.x;            // one block per center
    int tid = threadIdx.x;         // 256 threads
    const float* row = C + (size_t)k * DSTR;
    double sum = 0.0;
    for (int i = tid; i < DSTR; i += 256) {
        float v = row[i];
        sum += (double)v * (double)v;
        if (i < DIM) g_cpad[(size_t)k * DIM + i] = v;
    }
    __shared__ double red[8];
    #pragma unroll
    for (int o = 16; o > 0; o >>= 1) sum += __shfl_xor_sync(0xffffffffu, sum, o);
    if ((tid & 31) == 0) red[tid >> 5] = sum;
    __syncthreads();
    if (tid == 0) {
        double s = 0.0;
        #pragma unroll
        for (int w = 0; w < 8; w++) s += red[w];
        g_halfc[k] = (float)(0.5 * s);
        g_clast[k] = row[DIM];
    }
}

// ---------- per-row inverse norm (fp64 accumulate, scalar loads) ----------
__global__ void k_row_inv(const float* __restrict__ A) {
    int row  = (blockIdx.x * blockDim.x + threadIdx.x) >> 5;
    int lane = threadIdx.x & 31;
    if (row >= NROWS) return;
    const float* p = A + (size_t)row * DIM;
    double sum = 0.0;
    for (int i = lane; i < DIM; i += 32) {
        float v = p[i];
        sum += (double)v * (double)v;
    }
    #pragma unroll
    for (int o = 16; o > 0; o >>= 1) sum += __shfl_xor_sync(0xffffffffu, sum, o);
    if (lane == 0) g_inv[row] = (float)(1.0 / sqrt(sum + 1.0));
}

// ---------- simple tiled SGEMM: S[m][n] = sum_k A[m][k] * Cpad[n][k] ----------
// 64x64 tile, BK=8, 256 threads, 4x4 microtile, scalar loads only.
__global__ __launch_bounds__(256) void k_gemm(const float* __restrict__ A) {
    __shared__ float As[8][64];   // [k][m]
    __shared__ float Bs[8][64];   // [k][n]
    const int tid = threadIdx.x;
    const int tx = tid & 15;      // n direction, 0..15
    const int ty = tid >> 4;      // m direction, 0..15
    const int m0 = blockIdx.y * 64;
    const int n0 = blockIdx.x * 64;

    float acc[4][4];
    #pragma unroll
    for (int i = 0; i < 4; i++)
        #pragma unroll
        for (int j = 0; j < 4; j++) acc[i][j] = 0.f;

    for (int k0 = 0; k0 < DIM; k0 += 8) {
        // 512 elements each of As/Bs; 256 threads -> 2 each
        #pragma unroll
        for (int t = tid; t < 512; t += 256) {
            int rr = t >> 3;      // 0..63 (m or n within tile)
            int kk = t & 7;       // 0..7
            As[kk][rr] = A[(size_t)(m0 + rr) * DIM + (k0 + kk)];
            Bs[kk][rr] = (n0 + rr < KC)
                       ? g_cpad[(size_t)(n0 + rr) * DIM + (k0 + kk)]
                       : 0.f;
        }
        __syncthreads();
        #pragma unroll
        for (int kk = 0; kk < 8; kk++) {
            float a[4], b[4];
            #pragma unroll
            for (int i = 0; i < 4; i++) a[i] = As[kk][ty * 4 + i];
            #pragma unroll
            for (int j = 0; j < 4; j++) b[j] = Bs[kk][tx * 4 + j];
            #pragma unroll
            for (int i = 0; i < 4; i++)
                #pragma unroll
                for (int j = 0; j < 4; j++)
                    acc[i][j] = fmaf(a[i], b[j], acc[i][j]);
        }
        __syncthreads();
    }

    #pragma unroll
    for (int i = 0; i < 4; i++) {
        int m = m0 + ty * 4 + i;
        #pragma unroll
        for (int j = 0; j < 4; j++) {
            int n = n0 + tx * 4 + j;
            if (n < KC) g_S[(size_t)m * KC + n] = acc[i][j];
        }
    }
}

// ---------- per-row argmin of distance == argmax of score ----------
// score(n) = inv_m * (dot + c_last[n]) - 0.5||c_n||^2 ; ties -> smallest n.
// Output dtype: FLOAT32. The harness supports float32/int32/bf16; the
// reference's int64 labels get coerced to float32. labelset==arange, so the
// label value equals pred; 0..999 is exact in fp32.
__global__ void k_argmin(float* __restrict__ out) {
    int row  = blockIdx.x * 8 + (threadIdx.x >> 5);
    int lane = threadIdx.x & 31;
    if (row >= NROWS) return;
    float invm = g_inv[row];
    const float* srow = g_S + (size_t)row * KC;

    float bs = -FLT_MAX;
    int   bn = 0x7FFFFFFF;
    for (int n = lane; n < KC; n += 32) {
        float s = fmaf(srow[n] + g_clast[n], invm, -g_halfc[n]);
        if (s > bs) { bs = s; bn = n; }          // ascending n per lane: first max kept
    }
    #pragma unroll
    for (int off = 16; off > 0; off >>= 1) {
        float so = __shfl_xor_sync(0xffffffffu, bs, off);
        int   no = __shfl_xor_sync(0xffffffffu, bn, off);
        if (so > bs || (so == bs && no < bn)) { bs = so; bn = no; }
    }
    if (lane == 0) out[row] = (float)bn;
}

extern "C" void kernel_launch(void* const* d_in, const int* in_sizes, int n_in,
                              void* d_out, int out_size) {
    (void)in_sizes; (void)n_in; (void)out_size;
    const float* feats = (const float*)d_in[0];   // [16384, 2048] fp32
    const float* initc = (const float*)d_in[1];   // [1000, 2049]  fp32
    float* out = (float*)d_out;                   // fp32 labels (== pred)

    k_prep_centers<<<KC, 256>>>(initc);
    k_row_inv<<<(NROWS * 32 + 255) / 256, 256>>>(feats);

    dim3 grid((KC + 63) / 64, NROWS / 64);        // (16, 256)
    k_gemm<<<grid, 256>>>(feats);

    k_argmin<<<NROWS / 8, 256>>>(out);
}

// round 8
// speedup vs baseline: 3.4571x; 3.4571x over previous
#include <cuda_runtime.h>
#include <cuda_bf16.h>
#include <float.h>
#include <cstdint>

#define NROWS 16384
#define DIM   2048
#define DSTR  2049
#define KC    1000
#define NPAD  1024
#define NSTEPS 192           // 3 segments * (2048/32)
#define STAGE_BYTES 20480    // A tile 10240 + B tile 10240 (128 rows * 80B)
#define NSTAGE 3
#define SM_TOTAL (NSTAGE * STAGE_BYTES)

// ---------------- scratch ----------------
__device__ unsigned long long g_best[NROWS];
__device__ float g_inv[NROWS];
__device__ float g_halfc[NPAD];
__device__ float g_clast[NPAD];
__device__ __nv_bfloat16 g_ahi[(size_t)NROWS * DIM];
__device__ __nv_bfloat16 g_alo[(size_t)NROWS * DIM];
__device__ __nv_bfloat16 g_chi[(size_t)NPAD * DIM];
__device__ __nv_bfloat16 g_clo[(size_t)NPAD * DIM];

__device__ __forceinline__ uint32_t smem_u32(const void* p) {
    uint32_t a;
    asm("{ .reg .u64 t; cvta.to.shared.u64 t, %1; cvt.u32.u64 %0, t; }" : "=r"(a) : "l"(p));
    return a;
}
__device__ __forceinline__ void cp16(uint32_t saddr, const void* gptr) {
    asm volatile("cp.async.cg.shared.global [%0], [%1], 16;"
                 :: "r"(saddr), "l"(__cvta_generic_to_global(gptr)));
}
#define CP_COMMIT() asm volatile("cp.async.commit_group;" ::: "memory")
#define CP_WAIT(n)  asm volatile("cp.async.wait_group %0;" :: "n"(n) : "memory")

__device__ __forceinline__ void ldmx4(uint32_t* r, uint32_t addr) {
    asm volatile("ldmatrix.sync.aligned.m8n8.x4.shared.b16 {%0,%1,%2,%3}, [%4];"
                 : "=r"(r[0]), "=r"(r[1]), "=r"(r[2]), "=r"(r[3]) : "r"(addr));
}
__device__ __forceinline__ void mma16816(float* d, const uint32_t* a, const uint32_t* b) {
    asm volatile(
        "mma.sync.aligned.m16n8k16.row.col.f32.bf16.bf16.f32 "
        "{%0,%1,%2,%3}, {%4,%5,%6,%7}, {%8,%9}, {%0,%1,%2,%3};"
        : "+f"(d[0]), "+f"(d[1]), "+f"(d[2]), "+f"(d[3])
        : "r"(a[0]), "r"(a[1]), "r"(a[2]), "r"(a[3]), "r"(b[0]), "r"(b[1]));
}

// ---------------- prep kernels (validated in R6, plus bf16 split) ----------------
__global__ void k_init_best() {
    int i = blockIdx.x * blockDim.x + threadIdx.x;
    if (i < NROWS) g_best[i] = 0ull;
}

__global__ void k_convert_feats(const float* __restrict__ A) {
    size_t i4 = (size_t)blockIdx.x * blockDim.x + threadIdx.x;
    if (i4 >= (size_t)NROWS * DIM / 4) return;
    float4 v = ((const float4*)A)[i4];
    float f[4] = {v.x, v.y, v.z, v.w};
    __nv_bfloat16 h[4], l[4];
    #pragma unroll
    for (int j = 0; j < 4; j++) {
        h[j] = __float2bfloat16(f[j]);
        l[j] = __float2bfloat16(f[j] - __bfloat162float(h[j]));
    }
    ((ushort4*)g_ahi)[i4] = make_ushort4(__bfloat16_as_ushort(h[0]), __bfloat16_as_ushort(h[1]),
                                         __bfloat16_as_ushort(h[2]), __bfloat16_as_ushort(h[3]));
    ((ushort4*)g_alo)[i4] = make_ushort4(__bfloat16_as_ushort(l[0]), __bfloat16_as_ushort(l[1]),
                                         __bfloat16_as_ushort(l[2]), __bfloat16_as_ushort(l[3]));
}

__global__ void k_prep_centers(const float* __restrict__ C) {
    int k = blockIdx.x;          // 0..1023
    int tid = threadIdx.x;       // 256
    if (k >= KC) {
        for (int i = tid; i < DIM; i += 256) {
            g_chi[(size_t)k * DIM + i] = __float2bfloat16(0.f);
            g_clo[(size_t)k * DIM + i] = __float2bfloat16(0.f);
        }
        if (tid == 0) { g_halfc[k] = 1e30f; g_clast[k] = 0.f; }  // pad: never wins
        return;
    }
    const float* row = C + (size_t)k * DSTR;
    double sum = 0.0;
    for (int i = tid; i < DSTR; i += 256) {
        float v = row[i];
        sum += (double)v * (double)v;
        if (i < DIM) {
            __nv_bfloat16 h = __float2bfloat16(v);
            g_chi[(size_t)k * DIM + i] = h;
            g_clo[(size_t)k * DIM + i] = __float2bfloat16(v - __bfloat162float(h));
        }
    }
    __shared__ double red[8];
    #pragma unroll
    for (int o = 16; o > 0; o >>= 1) sum += __shfl_xor_sync(0xffffffffu, sum, o);
    if ((tid & 31) == 0) red[tid >> 5] = sum;
    __syncthreads();
    if (tid == 0) {
        double s = 0.0;
        #pragma unroll
        for (int w = 0; w < 8; w++) s += red[w];
        g_halfc[k] = (float)(0.5 * s);
        g_clast[k] = row[DIM];
    }
}

__global__ void k_row_inv(const float* __restrict__ A) {
    int row  = (blockIdx.x * blockDim.x + threadIdx.x) >> 5;
    int lane = threadIdx.x & 31;
    if (row >= NROWS) return;
    const float* p = A + (size_t)row * DIM;
    double sum = 0.0;
    for (int i = lane; i < DIM; i += 32) {
        float v = p[i];
        sum += (double)v * (double)v;
    }
    #pragma unroll
    for (int o = 16; o > 0; o >>= 1) sum += __shfl_xor_sync(0xffffffffu, sum, o);
    if (lane == 0) g_inv[row] = (float)(1.0 / sqrt(sum + 1.0));
}

// ---------------- HMMA bf16-split GEMM + fused argmax ----------------
// smem stage: A[128 rows][80B] then B[128 rows][80B]; only first 64B of each row used.
// 80B row stride => ldmatrix 8-row reads hit all 32 banks (conflict-free).
__global__ __launch_bounds__(256) void k_gemm_mma() {
    extern __shared__ char smem[];
    const uint32_t sb = smem_u32(smem);
    const int tid = threadIdx.x;
    const int wid = tid >> 5, lane = tid & 31;
    const int gid = lane >> 2, tig = lane & 3;
    const int n0 = blockIdx.x * 128;
    const int m0 = blockIdx.y * 128;
    const int wm = wid >> 1;       // 0..3, 32 m-rows
    const int wn = wid & 1;        // 0..1, 64 n-cols

    float acc[2][8][4];
    #pragma unroll
    for (int a = 0; a < 2; a++)
        #pragma unroll
        for (int b = 0; b < 8; b++)
            #pragma unroll
            for (int c = 0; c < 4; c++) acc[a][b][c] = 0.f;

    // global->smem: 4 cp.async of 16B per thread per stage
    const int rc = tid >> 2;              // 0..63
    const int cc = tid & 3;               // 16B chunk in 64B row slab

    // ldmatrix per-lane base offsets (bytes within a stage)
    const uint32_t aoff = (uint32_t)((wm * 32 + (lane & 15)) * 80 + (lane >> 4) * 16);
    const uint32_t boff = (uint32_t)((wn * 64 + (lane & 7) + ((lane >> 4) << 3)) * 80
                                     + ((lane >> 3) & 1) * 16);

    #define LOAD_STAGE(s, st) do {                                              \
        int seg_ = (s) >> 6;                                                    \
        int k0_  = ((s) & 63) << 5;                                             \
        const __nv_bfloat16* Ag_ = (seg_ == 2) ? g_alo : g_ahi;                 \
        const __nv_bfloat16* Bg_ = (seg_ == 1) ? g_clo : g_chi;                 \
        uint32_t sa_ = sb + (st) * STAGE_BYTES;                                 \
        uint32_t sbb_ = sa_ + 10240;                                            \
        cp16(sa_  + rc * 80 + cc * 16,        Ag_ + (size_t)(m0 + rc) * DIM + k0_ + cc * 8); \
        cp16(sa_  + (rc + 64) * 80 + cc * 16, Ag_ + (size_t)(m0 + rc + 64) * DIM + k0_ + cc * 8); \
        cp16(sbb_ + rc * 80 + cc * 16,        Bg_ + (size_t)(n0 + rc) * DIM + k0_ + cc * 8); \
        cp16(sbb_ + (rc + 64) * 80 + cc * 16, Bg_ + (size_t)(n0 + rc + 64) * DIM + k0_ + cc * 8); \
    } while (0)

    LOAD_STAGE(0, 0); CP_COMMIT();
    LOAD_STAGE(1, 1); CP_COMMIT();

    for (int s = 0; s < NSTEPS; ++s) {
        CP_WAIT(1);
        __syncthreads();
        if (s + 2 < NSTEPS) LOAD_STAGE(s + 2, (s + 2) % NSTAGE);
        CP_COMMIT();

        const uint32_t stA = sb + (s % NSTAGE) * STAGE_BYTES;
        const uint32_t stB = stA + 10240;
        #pragma unroll
        for (int kk = 0; kk < 2; ++kk) {
            uint32_t af[2][4];
            ldmx4(af[0], stA + aoff + kk * 32);
            ldmx4(af[1], stA + aoff + 1280 + kk * 32);   // mfrag1: +16 rows * 80B
            uint32_t bf[8][2];
            #pragma unroll
            for (int np = 0; np < 4; ++np) {
                uint32_t r[4];
                ldmx4(r, stB + boff + np * 1280 + kk * 32);
                bf[2 * np][0] = r[0]; bf[2 * np][1] = r[1];
                bf[2 * np + 1][0] = r[2]; bf[2 * np + 1][1] = r[3];
            }
            #pragma unroll
            for (int mf = 0; mf < 2; ++mf)
                #pragma unroll
                for (int nf = 0; nf < 8; ++nf)
                    mma16816(acc[mf][nf], af[mf], bf[nf]);
        }
    }

    // -------- fused epilogue: score + argmax from registers --------
    // thread cols: n = n0 + wn*64 + nf*8 + 2*tig + j
    float cl[16], hc[16];
    #pragma unroll
    for (int nf = 0; nf < 8; ++nf)
        #pragma unroll
        for (int j = 0; j < 2; ++j) {
            int n = n0 + wn * 64 + nf * 8 + 2 * tig + j;
            cl[nf * 2 + j] = g_clast[n];
            hc[nf * 2 + j] = g_halfc[n];
        }

    #pragma unroll
    for (int mf = 0; mf < 2; ++mf)
        #pragma unroll
        for (int h = 0; h < 2; ++h) {
            int m = m0 + wm * 32 + mf * 16 + gid + 8 * h;
            float invm = g_inv[m];
            float bs = -FLT_MAX;
            int bn = 0x7FFFFFFF;
            #pragma unroll
            for (int nf = 0; nf < 8; ++nf)
                #pragma unroll
                for (int j = 0; j < 2; ++j) {
                    float s = fmaf(acc[mf][nf][2 * h + j] + cl[nf * 2 + j], invm,
                                   -hc[nf * 2 + j]);
                    int n = n0 + wn * 64 + nf * 8 + 2 * tig + j;
                    if (s > bs) { bs = s; bn = n; }   // ascending n: first max kept
                }
            #pragma unroll
            for (int o = 1; o <= 2; o <<= 1) {
                float so = __shfl_xor_sync(0xffffffffu, bs, o);
                int   no = __shfl_xor_sync(0xffffffffu, bn, o);
                if (so > bs || (so == bs && no < bn)) { bs = so; bn = no; }
            }
            if (tig == 0) {
                unsigned sbits = __float_as_uint(bs);
                sbits = (sbits & 0x80000000u) ? ~sbits : (sbits | 0x80000000u);
                unsigned long long packed = ((unsigned long long)sbits << 32)
                    | (unsigned long long)(0xFFFFFFFFu - (unsigned)bn);
                atomicMax(&g_best[m], packed);
            }
        }
}

__global__ void k_decode(float* __restrict__ out) {
    int i = blockIdx.x * blockDim.x + threadIdx.x;
    if (i < NROWS)
        out[i] = (float)(0xFFFFFFFFu - (unsigned)(g_best[i] & 0xFFFFFFFFull));
}

extern "C" void kernel_launch(void* const* d_in, const int* in_sizes, int n_in,
                              void* d_out, int out_size) {
    (void)in_sizes; (void)n_in; (void)out_size;
    const float* feats = (const float*)d_in[0];
    const float* initc = (const float*)d_in[1];
    float* out = (float*)d_out;

    cudaFuncSetAttribute(k_gemm_mma, cudaFuncAttributeMaxDynamicSharedMemorySize, SM_TOTAL);

    k_init_best<<<(NROWS + 255) / 256, 256>>>();
    k_convert_feats<<<(NROWS * DIM / 4 + 255) / 256, 256>>>(feats);
    k_prep_centers<<<NPAD, 256>>>(initc);
    k_row_inv<<<(NROWS * 32 + 255) / 256, 256>>>(feats);

    dim3 grid(NPAD / 128, NROWS / 128);   // (8, 128)
    k_gemm_mma<<<grid, 256, SM_TOTAL>>>();

    k_decode<<<(NROWS + 255) / 256, 256>>>(out);
}